// round 15
// baseline (speedup 1.0000x reference)
#include <cuda_runtime.h>
#include <cuda_bf16.h>
#include <cstdint>

#define R_TOTAL 32768   // B*N rows
#define KCODES  8192
#define DDIM    512
#define NTILES  512     // 16-wide code tiles for screening
#define MARGIN  2.5e-4f

// ---------------- static scratch (no allocations allowed) ----------------
__device__ float         g_rowA[R_TOTAL];
__device__ float         g_enorm[KCODES];
__device__ float         g_rowpart[R_TOTAL];
__device__ unsigned long long g_best[R_TOTAL];           // (dist_bits<<32)|code
__device__ int           g_tcnt[NTILES];
__device__ int           g_work[131072];                 // (tile<<16)|chunk128
__device__ int           g_nwork;
__device__ __nv_bfloat16 g_zb[(size_t)R_TOTAL * DDIM];   // 32 MB
__device__ __nv_bfloat16 g_eb[(size_t)KCODES * DDIM];    //  8 MB
__device__ float         g_tilemin[(size_t)R_TOTAL * NTILES]; // 64 MB
__device__ int           g_lists[(size_t)NTILES * R_TOTAL];   // 64 MB row lists

__device__ __forceinline__ uint32_t smaddr(const void* p) {
    return (uint32_t)__cvta_generic_to_shared(p);
}
#define CP16(dst, src) \
    asm volatile("cp.async.cg.shared.global [%0], [%1], 16;" :: "r"(dst), "l"(src))
#define CP_COMMIT() asm volatile("cp.async.commit_group;")

// ---------------------------------------------------------------------------
// Row sum-of-squares (reference-exact NEON 4-lane emulation), z + embed fused.
// ---------------------------------------------------------------------------
__global__ void rownorm_kernel(const float* __restrict__ z,
                               const float* __restrict__ embed) {
    int gid  = blockIdx.x * blockDim.x + threadIdx.x;
    int row  = gid >> 2;
    int lane = gid & 3;
    if (row >= R_TOTAL + KCODES) return;
    const float* p = (row < R_TOTAL) ? (z + (size_t)row * DDIM)
                                     : (embed + (size_t)(row - R_TOTAL) * DDIM);
    float acc = 0.0f;
    #pragma unroll 8
    for (int i = lane; i < DDIM; i += 4) {
        float v = p[i];
        acc = __fadd_rn(acc, __fmul_rn(v, v));
    }
    float o  = __shfl_xor_sync(0xFFFFFFFF, acc, 2);
    float s  = __fadd_rn(acc, o);
    float o2 = __shfl_xor_sync(0xFFFFFFFF, s, 1);
    float A  = __fadd_rn(s, o2);
    if (lane == 0) {
        if (row < R_TOTAL) g_rowA[row] = A;
        else               g_enorm[row - R_TOTAL] = A;
    }
}

// ---------------------------------------------------------------------------
// fp32 -> bf16 conversion of z and embed; zero tile counters + work counter.
// ---------------------------------------------------------------------------
__global__ void convert_kernel(const float* __restrict__ z,
                               const float* __restrict__ embed) {
    const int NZ = R_TOTAL * DDIM / 4;
    const int NE = KCODES * DDIM / 4;
    int i = blockIdx.x * blockDim.x + threadIdx.x;
    if (i < NTILES) g_tcnt[i] = 0;
    if (i == NTILES) g_nwork = 0;
    if (i < NZ) {
        float4 v = ((const float4*)z)[i];
        ((__nv_bfloat162*)g_zb)[i * 2 + 0] = __floats2bfloat162_rn(v.x, v.y);
        ((__nv_bfloat162*)g_zb)[i * 2 + 1] = __floats2bfloat162_rn(v.z, v.w);
    } else if (i < NZ + NE) {
        int j = i - NZ;
        float4 v = ((const float4*)embed)[j];
        ((__nv_bfloat162*)g_eb)[j * 2 + 0] = __floats2bfloat162_rn(v.x, v.y);
        ((__nv_bfloat162*)g_eb)[j * 2 + 1] = __floats2bfloat162_rn(v.z, v.w);
    }
}

// ---------------------------------------------------------------------------
// Screening GEMM (R13 + hoisted prefetch): bf16 mma.sync m16n8k16, CTA 128 thr
// (2x2 warps), CTA tile 128x128, warp tile 64x64, GBK=64 (128-B rows,
// ROWST=144), 3-stage cp.async, fine-grained LDSM/HMMA interleave, 2 CTAs/SM.
// ---------------------------------------------------------------------------
#define GBK       64                   // bf16 elements per chunk (128 B)
#define NKT       (DDIM / GBK)         // 8
#define ROWST     144
#define HALF_ST   (128 * ROWST)        // 18432
#define STAGE_B   (2 * HALF_ST)        // 36864
#define NSTAGE    3
#define SM_TOTAL  (NSTAGE * STAGE_B)   // 110592

__global__ void __launch_bounds__(128, 2) screen_gemm_kernel() {
    extern __shared__ __align__(128) char sm[];

    const int tid   = threadIdx.x;
    const int wid   = tid >> 5;
    const int lane  = tid & 31;
    const int warpY = wid & 1;
    const int warpX = wid >> 1;
    const int row0  = blockIdx.x * 128;
    const int n0    = blockIdx.y * 128;

    float acc[4][8][4];
    #pragma unroll
    for (int m = 0; m < 4; m++)
        #pragma unroll
        for (int n = 0; n < 8; n++)
            #pragma unroll
            for (int p = 0; p < 4; p++) acc[m][n][p] = 0.0f;

    const __nv_bfloat16* zsrc = g_zb + (size_t)row0 * DDIM;
    const __nv_bfloat16* esrc = g_eb + (size_t)n0 * DDIM;

#define LOAD_TILE(kt) do {                                                     \
    int st_ = (kt) % NSTAGE;                                                   \
    int k0_ = (kt) * GBK;                                                      \
    uint32_t ab = smaddr(sm + st_ * STAGE_B);                                  \
    _Pragma("unroll")                                                          \
    for (int u = 0; u < 8; u++) {                                              \
        int c = tid + u * 128;                                                 \
        int r = c >> 3, h = (c & 7) * 8;                                       \
        CP16(ab + r * ROWST + h * 2, zsrc + (size_t)r * DDIM + k0_ + h);       \
        CP16(ab + HALF_ST + r * ROWST + h * 2,                                 \
             esrc + (size_t)r * DDIM + k0_ + h);                               \
    }                                                                          \
    CP_COMMIT();                                                               \
} while (0)

    const int i8 = lane & 7, q = lane >> 3;
    const int a_row  = warpY * 64 + (q & 1) * 8 + i8;
    const int a_colb = (q >> 1) * 16;
    const int b_row  = warpX * 64 + (q >> 1) * 8 + i8;
    const int b_colb = (q & 1) * 16;

    uint32_t fa[2][4][4], fb[2][4][4];

#define LDSM_A1(buf, base, ks, m) do {                                         \
    uint32_t addr = (base) + (uint32_t)(a_row + (m) * 16) * ROWST              \
                  + (ks) * 32 + a_colb;                                        \
    asm volatile("ldmatrix.sync.aligned.m8n8.x4.shared.b16 {%0,%1,%2,%3}, [%4];" \
        : "=r"(fa[buf][m][0]), "=r"(fa[buf][m][1]),                            \
          "=r"(fa[buf][m][2]), "=r"(fa[buf][m][3])                             \
        : "r"(addr));                                                          \
} while (0)

#define LDSM_B1(buf, base, ks, pr) do {                                        \
    uint32_t addr = (base) + HALF_ST                                           \
                  + (uint32_t)(b_row + (pr) * 16) * ROWST                      \
                  + (ks) * 32 + b_colb;                                        \
    asm volatile("ldmatrix.sync.aligned.m8n8.x4.shared.b16 {%0,%1,%2,%3}, [%4];" \
        : "=r"(fb[buf][pr][0]), "=r"(fb[buf][pr][1]),                          \
          "=r"(fb[buf][pr][2]), "=r"(fb[buf][pr][3])                           \
        : "r"(addr));                                                          \
} while (0)

#define HMMA_M(buf, m) do {                                                    \
    _Pragma("unroll")                                                          \
    for (int n = 0; n < 8; n++) {                                              \
        const int pr = n >> 1, ro = (n & 1) * 2;                               \
        asm volatile(                                                          \
            "mma.sync.aligned.m16n8k16.row.col.f32.bf16.bf16.f32 "             \
            "{%0,%1,%2,%3}, {%4,%5,%6,%7}, {%8,%9}, {%0,%1,%2,%3};"            \
            : "+f"(acc[m][n][0]), "+f"(acc[m][n][1]),                          \
              "+f"(acc[m][n][2]), "+f"(acc[m][n][3])                           \
            : "r"(fa[buf][m][0]), "r"(fa[buf][m][1]),                          \
              "r"(fa[buf][m][2]), "r"(fa[buf][m][3]),                          \
              "r"(fb[buf][pr][ro]), "r"(fb[buf][pr][ro + 1]));                 \
    }                                                                          \
} while (0)

#define STEP(ldbuf, base, ks, mmabuf) do {                                     \
    LDSM_B1(ldbuf, base, ks, 0); LDSM_B1(ldbuf, base, ks, 1);                  \
    HMMA_M(mmabuf, 0);                                                         \
    LDSM_B1(ldbuf, base, ks, 2); LDSM_B1(ldbuf, base, ks, 3);                  \
    HMMA_M(mmabuf, 1);                                                         \
    LDSM_A1(ldbuf, base, ks, 0); LDSM_A1(ldbuf, base, ks, 1);                  \
    HMMA_M(mmabuf, 2);                                                         \
    LDSM_A1(ldbuf, base, ks, 2); LDSM_A1(ldbuf, base, ks, 3);                  \
    HMMA_M(mmabuf, 3);                                                         \
} while (0)

    LOAD_TILE(0);
    LOAD_TILE(1);
    asm volatile("cp.async.wait_group 1;");
    __syncthreads();
    {
        const uint32_t b0 = smaddr(sm);
        #pragma unroll
        for (int m = 0; m < 4; m++) LDSM_A1(0, b0, 0, m);
        #pragma unroll
        for (int pr = 0; pr < 4; pr++) LDSM_B1(0, b0, 0, pr);
    }

    #pragma unroll 1
    for (int kt = 0; kt < NKT; kt++) {
        const uint32_t abase = smaddr(sm + (kt % NSTAGE) * STAGE_B);
        if (kt + 2 < NKT) LOAD_TILE(kt + 2);   // hoisted: stage (kt-1)%3 free
        STEP(1, abase, 1, 0);
        STEP(0, abase, 2, 1);
        STEP(1, abase, 3, 0);
        if (kt + 1 < NKT) {
            if (kt + 2 < NKT) asm volatile("cp.async.wait_group 1;");
            else              asm volatile("cp.async.wait_group 0;");
            __syncthreads();
            const uint32_t nbase = smaddr(sm + ((kt + 1) % NSTAGE) * STAGE_B);
            STEP(0, nbase, 0, 1);
        } else {
            #pragma unroll
            for (int m = 0; m < 4; m++) HMMA_M(1, m);
        }
    }
#undef LOAD_TILE
#undef LDSM_A1
#undef LDSM_B1
#undef HMMA_M
#undef STEP

    // ---- epilogue: approx dist + per-(row, 16-code subtile) min ----
    const int g  = lane >> 2;
    const int qc = lane & 3;

    float en[8][2];
    #pragma unroll
    for (int n = 0; n < 8; n++) {
        int col = n0 + warpX * 64 + n * 8 + qc * 2;
        en[n][0] = g_enorm[col];
        en[n][1] = g_enorm[col + 1];
    }

    #pragma unroll
    for (int m = 0; m < 4; m++) {
        #pragma unroll
        for (int h = 0; h < 2; h++) {
            int grow = row0 + warpY * 64 + m * 16 + g + h * 8;
            float Ar = g_rowA[grow];
            #pragma unroll
            for (int s = 0; s < 4; s++) {
                float v = 3.402823466e+38f;
                #pragma unroll
                for (int nn = 0; nn < 2; nn++) {
                    int n = s * 2 + nn;
                    #pragma unroll
                    for (int p = 0; p < 2; p++) {
                        float d = Ar - 2.0f * acc[m][n][h * 2 + p] + en[n][p];
                        v = fminf(v, d);
                    }
                }
                v = fminf(v, __shfl_xor_sync(0xFFFFFFFF, v, 1));
                v = fminf(v, __shfl_xor_sync(0xFFFFFFFF, v, 2));
                if (qc == 0)
                    g_tilemin[(size_t)grow * NTILES + blockIdx.y * 8 + warpX * 4 + s] = v;
            }
        }
    }
}

// ---------------------------------------------------------------------------
// Pass 1: candidate selection (unchanged). Appends rows to tile lists.
// ---------------------------------------------------------------------------
__global__ void __launch_bounds__(256) candsel_kernel() {
    const int wid  = threadIdx.x >> 5;
    const int lane = threadIdx.x & 31;
    const int row  = blockIdx.x * 8 + wid;

    float tm[16];
    #pragma unroll
    for (int j = 0; j < 16; j++)
        tm[j] = g_tilemin[(size_t)row * NTILES + lane + 32 * j];

    float rmin = tm[0];
    #pragma unroll
    for (int j = 1; j < 16; j++) rmin = fminf(rmin, tm[j]);
    #pragma unroll
    for (int o = 16; o > 0; o >>= 1)
        rmin = fminf(rmin, __shfl_xor_sync(0xFFFFFFFF, rmin, o));

    if (lane == 0) g_best[row] = 0xFFFFFFFFFFFFFFFFull;

    const float thr = rmin + MARGIN;
    #pragma unroll
    for (int j = 0; j < 16; j++) {
        int tile = lane + 32 * j;
        if (tm[j] <= thr) {
            int pos = atomicAdd(&g_tcnt[tile], 1);
            g_lists[(size_t)tile * R_TOTAL + pos] = row;
        }
    }
}

// ---------------------------------------------------------------------------
// Pass 1.5: build compact work list — one item per (tile, 128-row chunk).
// ---------------------------------------------------------------------------
#define ROWS_PER_ITEM 128
__global__ void worklist_kernel() {
    const int t = threadIdx.x;          // 512 threads, 1 block
    int cnt = g_tcnt[t];
    int items = (cnt + ROWS_PER_ITEM - 1) / ROWS_PER_ITEM;
    if (items > 0) {
        int base = atomicAdd(&g_nwork, items);
        for (int c = 0; c < items; c++)
            g_work[base + c] = (t << 16) | c;
    }
}

// ---------------------------------------------------------------------------
// Pass 2: work-item rescore. A block claims items grid-stride; per item it
// stages the tile's 16 codes ONCE and scores up to 128 rows (8 per half-warp
// slot) with the bit-exact ascending-k fmaf chain; merge via atomicMin on the
// packed (dist_bits, code) u64 == lexicographic (val, idx) argmin.
// ---------------------------------------------------------------------------
__global__ void __launch_bounds__(256) rescore3_kernel(
    const float* __restrict__ z,
    const float* __restrict__ embed)
{
    __shared__ float ecod[16 * 513];
    const int wid  = threadIdx.x >> 5;
    const int lane = threadIdx.x & 31;
    const int half = lane >> 4;
    const int l16  = lane & 15;
    const int slot = wid * 2 + half;            // 0..15

    for (int it = blockIdx.x; it < g_nwork; it += gridDim.x) {
        const int w     = g_work[it];
        const int tile  = w >> 16;
        const int chunk = w & 0xFFFF;
        const int count = g_tcnt[tile];

        __syncthreads();   // previous item's readers done before restage
        for (int idx = threadIdx.x; idx < 16 * DDIM; idx += 256) {
            int r = idx >> 9, k = idx & 511;
            ecod[r * 513 + k] = embed[((size_t)tile * 16 + r) * DDIM + k];
        }
        __syncthreads();

        const int   code = tile * 16 + l16;
        const float C    = g_enorm[code];
        const float* ec  = ecod + l16 * 513;
        const int   base = chunk * ROWS_PER_ITEM;

        #pragma unroll 1
        for (int s = 0; s < ROWS_PER_ITEM / 16; s++) {
            const int i = base + slot + s * 16;
            if (i >= count) break;
            const int row = g_lists[(size_t)tile * R_TOTAL + i];
            const float* zr = z + (size_t)row * DDIM;
            const float A = g_rowA[row];
            float dot = 0.0f;
            #pragma unroll 16
            for (int k = 0; k < DDIM; k++)
                dot = fmaf(zr[k], ec[k], dot);
            float B2   = 2.0f * dot;
            float tt   = __fadd_rn(A, -B2);
            float dist = __fadd_rn(tt, C);

            float bv = dist;
            int   bi = code;
            #pragma unroll
            for (int o = 8; o > 0; o >>= 1) {
                float ov = __shfl_xor_sync(0xFFFFFFFF, bv, o);
                int   oi = __shfl_xor_sync(0xFFFFFFFF, bi, o);
                if (ov < bv || (ov == bv && oi < bi)) { bv = ov; bi = oi; }
            }
            if (l16 == 0) {
                unsigned long long pk =
                    ((unsigned long long)__float_as_uint(bv) << 32) | (unsigned)bi;
                atomicMin(&g_best[row], pk);
            }
        }
    }
}

// ---------------------------------------------------------------------------
// Pass 3: finalize — unpack best code, gather z_q, loss partial, codes out.
// ---------------------------------------------------------------------------
__global__ void gather_kernel(const float* __restrict__ z,
                              const float* __restrict__ embed,
                              float* __restrict__ out_zq,
                              float* __restrict__ codes_f) {
    const int row = blockIdx.x;
    const int t   = threadIdx.x;
    const int c   = (int)(g_best[row] & 0xFFFFFFFFull);
    if (t == 0 && codes_f) codes_f[row] = (float)c;
    float4 e  = *(const float4*)(embed + (size_t)c * DDIM + t * 4);
    float4 zz = *(const float4*)(z + (size_t)row * DDIM + t * 4);
    *(float4*)(out_zq + (size_t)row * DDIM + t * 4) = e;
    float dx = zz.x - e.x, dy = zz.y - e.y, dz = zz.z - e.z, dw = zz.w - e.w;
    float s = dx * dx + dy * dy + dz * dz + dw * dw;
    __shared__ float red[128];
    red[t] = s;
    __syncthreads();
    #pragma unroll
    for (int o = 64; o > 0; o >>= 1) {
        if (t < o) red[t] += red[t + o];
        __syncthreads();
    }
    if (t == 0) g_rowpart[row] = red[0];
}

__global__ void loss_kernel(float* __restrict__ out_loss) {
    const int t = threadIdx.x;
    float s = 0.0f;
    for (int i = t; i < R_TOTAL; i += 1024) s += g_rowpart[i];
    __shared__ float red[1024];
    red[t] = s;
    __syncthreads();
    for (int o = 512; o > 0; o >>= 1) {
        if (t < o) red[t] += red[t + o];
        __syncthreads();
    }
    if (t == 0) out_loss[0] = 0.1f * (red[0] / 16777216.0f);
}

// ---------------------------------------------------------------------------
extern "C" void kernel_launch(void* const* d_in, const int* in_sizes, int n_in,
                              void* d_out, int out_size) {
    const float* z     = (const float*)d_in[0];   // (8,4096,512) f32
    const float* embed = (const float*)d_in[1];   // (8192,512) f32
    float* out = (float*)d_out;

    const long long ZQ_ELEMS = (long long)R_TOTAL * DDIM;
    float* out_zq    = out;
    float* out_codes = 0;
    float* out_loss  = 0;
    if ((long long)out_size >= ZQ_ELEMS + R_TOTAL + 1) {
        out_codes = out + ZQ_ELEMS;
        out_loss  = out + ZQ_ELEMS + R_TOTAL;
    }

    static int init_done = 0;
    if (!init_done) {
        cudaFuncSetAttribute(screen_gemm_kernel,
                             cudaFuncAttributeMaxDynamicSharedMemorySize, SM_TOTAL);
        init_done = 1;
    }

    const int NCONV = (R_TOTAL * DDIM + KCODES * DDIM) / 4;
    convert_kernel<<<(NCONV + 255) / 256, 256>>>(z, embed);

    rownorm_kernel<<<((R_TOTAL + KCODES) * 4 + 255) / 256, 256>>>(z, embed);

    dim3 gg(R_TOTAL / 128, KCODES / 128);   // (256, 64)
    screen_gemm_kernel<<<gg, 128, SM_TOTAL>>>();

    candsel_kernel<<<R_TOTAL / 8, 256>>>();

    worklist_kernel<<<1, NTILES>>>();

    rescore3_kernel<<<2048, 256>>>(z, embed);

    gather_kernel<<<R_TOTAL, 128>>>(z, embed, out_zq, out_codes);

    if (out_loss) loss_kernel<<<1, 1024>>>(out_loss);
}

// round 16
// speedup vs baseline: 1.1431x; 1.1431x over previous
#include <cuda_runtime.h>
#include <cuda_bf16.h>
#include <cstdint>

#define R_TOTAL 32768   // B*N rows
#define KCODES  8192
#define DDIM    512
#define NTILES  512     // 16-wide code tiles for screening
#define MARGIN  2.5e-4f

// ---------------- static scratch (no allocations allowed) ----------------
__device__ float         g_rowA[R_TOTAL];
__device__ float         g_enorm[KCODES];
__device__ float         g_rowpart[R_TOTAL];
__device__ unsigned long long g_best[R_TOTAL];           // (dist_bits<<32)|code
__device__ int           g_tcnt[NTILES];
__device__ __nv_bfloat16 g_zb[(size_t)R_TOTAL * DDIM];   // 32 MB
__device__ __nv_bfloat16 g_eb[(size_t)KCODES * DDIM];    //  8 MB
__device__ float         g_tilemin[(size_t)R_TOTAL * NTILES]; // 64 MB
__device__ int           g_lists[(size_t)NTILES * R_TOTAL];   // 64 MB row lists

__device__ __forceinline__ uint32_t smaddr(const void* p) {
    return (uint32_t)__cvta_generic_to_shared(p);
}
#define CP16(dst, src) \
    asm volatile("cp.async.cg.shared.global [%0], [%1], 16;" :: "r"(dst), "l"(src))
#define CP_COMMIT() asm volatile("cp.async.commit_group;")

// ---------------------------------------------------------------------------
// Row sum-of-squares (reference-exact NEON 4-lane emulation), z + embed fused.
// ---------------------------------------------------------------------------
__global__ void rownorm_kernel(const float* __restrict__ z,
                               const float* __restrict__ embed) {
    int gid  = blockIdx.x * blockDim.x + threadIdx.x;
    int row  = gid >> 2;
    int lane = gid & 3;
    if (row >= R_TOTAL + KCODES) return;
    const float* p = (row < R_TOTAL) ? (z + (size_t)row * DDIM)
                                     : (embed + (size_t)(row - R_TOTAL) * DDIM);
    float acc = 0.0f;
    #pragma unroll 8
    for (int i = lane; i < DDIM; i += 4) {
        float v = p[i];
        acc = __fadd_rn(acc, __fmul_rn(v, v));
    }
    float o  = __shfl_xor_sync(0xFFFFFFFF, acc, 2);
    float s  = __fadd_rn(acc, o);
    float o2 = __shfl_xor_sync(0xFFFFFFFF, s, 1);
    float A  = __fadd_rn(s, o2);
    if (lane == 0) {
        if (row < R_TOTAL) g_rowA[row] = A;
        else               g_enorm[row - R_TOTAL] = A;
    }
}

// ---------------------------------------------------------------------------
// fp32 -> bf16 conversion of z and embed; also zeroes the tile counters.
// ---------------------------------------------------------------------------
__global__ void convert_kernel(const float* __restrict__ z,
                               const float* __restrict__ embed) {
    const int NZ = R_TOTAL * DDIM / 4;
    const int NE = KCODES * DDIM / 4;
    int i = blockIdx.x * blockDim.x + threadIdx.x;
    if (i < NTILES) g_tcnt[i] = 0;
    if (i < NZ) {
        float4 v = ((const float4*)z)[i];
        ((__nv_bfloat162*)g_zb)[i * 2 + 0] = __floats2bfloat162_rn(v.x, v.y);
        ((__nv_bfloat162*)g_zb)[i * 2 + 1] = __floats2bfloat162_rn(v.z, v.w);
    } else if (i < NZ + NE) {
        int j = i - NZ;
        float4 v = ((const float4*)embed)[j];
        ((__nv_bfloat162*)g_eb)[j * 2 + 0] = __floats2bfloat162_rn(v.x, v.y);
        ((__nv_bfloat162*)g_eb)[j * 2 + 1] = __floats2bfloat162_rn(v.z, v.w);
    }
}

// ---------------------------------------------------------------------------
// Screening GEMM (R13/R14, proven): bf16 mma.sync m16n8k16, CTA 128 thr (2x2),
// CTA tile 128x128, warp tile 64x64, GBK=64 (128-B rows, ROWST=144),
// 3-stage cp.async, fine-grained LDSM/HMMA interleave, 2 CTAs/SM.
// ---------------------------------------------------------------------------
#define GBK       64                   // bf16 elements per chunk (128 B)
#define NKT       (DDIM / GBK)         // 8
#define ROWST     144
#define HALF_ST   (128 * ROWST)        // 18432
#define STAGE_B   (2 * HALF_ST)        // 36864
#define NSTAGE    3
#define SM_TOTAL  (NSTAGE * STAGE_B)   // 110592

__global__ void __launch_bounds__(128, 2) screen_gemm_kernel() {
    extern __shared__ __align__(128) char sm[];

    const int tid   = threadIdx.x;
    const int wid   = tid >> 5;
    const int lane  = tid & 31;
    const int warpY = wid & 1;
    const int warpX = wid >> 1;
    const int row0  = blockIdx.x * 128;
    const int n0    = blockIdx.y * 128;

    float acc[4][8][4];
    #pragma unroll
    for (int m = 0; m < 4; m++)
        #pragma unroll
        for (int n = 0; n < 8; n++)
            #pragma unroll
            for (int p = 0; p < 4; p++) acc[m][n][p] = 0.0f;

    const __nv_bfloat16* zsrc = g_zb + (size_t)row0 * DDIM;
    const __nv_bfloat16* esrc = g_eb + (size_t)n0 * DDIM;

#define LOAD_TILE(kt) do {                                                     \
    int st_ = (kt) % NSTAGE;                                                   \
    int k0_ = (kt) * GBK;                                                      \
    uint32_t ab = smaddr(sm + st_ * STAGE_B);                                  \
    _Pragma("unroll")                                                          \
    for (int u = 0; u < 8; u++) {                                              \
        int c = tid + u * 128;                                                 \
        int r = c >> 3, h = (c & 7) * 8;                                       \
        CP16(ab + r * ROWST + h * 2, zsrc + (size_t)r * DDIM + k0_ + h);       \
        CP16(ab + HALF_ST + r * ROWST + h * 2,                                 \
             esrc + (size_t)r * DDIM + k0_ + h);                               \
    }                                                                          \
    CP_COMMIT();                                                               \
} while (0)

    const int i8 = lane & 7, q = lane >> 3;
    const int a_row  = warpY * 64 + (q & 1) * 8 + i8;
    const int a_colb = (q >> 1) * 16;
    const int b_row  = warpX * 64 + (q >> 1) * 8 + i8;
    const int b_colb = (q & 1) * 16;

    uint32_t fa[2][4][4], fb[2][4][4];

#define LDSM_A1(buf, base, ks, m) do {                                         \
    uint32_t addr = (base) + (uint32_t)(a_row + (m) * 16) * ROWST              \
                  + (ks) * 32 + a_colb;                                        \
    asm volatile("ldmatrix.sync.aligned.m8n8.x4.shared.b16 {%0,%1,%2,%3}, [%4];" \
        : "=r"(fa[buf][m][0]), "=r"(fa[buf][m][1]),                            \
          "=r"(fa[buf][m][2]), "=r"(fa[buf][m][3])                             \
        : "r"(addr));                                                          \
} while (0)

#define LDSM_B1(buf, base, ks, pr) do {                                        \
    uint32_t addr = (base) + HALF_ST                                           \
                  + (uint32_t)(b_row + (pr) * 16) * ROWST                      \
                  + (ks) * 32 + b_colb;                                        \
    asm volatile("ldmatrix.sync.aligned.m8n8.x4.shared.b16 {%0,%1,%2,%3}, [%4];" \
        : "=r"(fb[buf][pr][0]), "=r"(fb[buf][pr][1]),                          \
          "=r"(fb[buf][pr][2]), "=r"(fb[buf][pr][3])                           \
        : "r"(addr));                                                          \
} while (0)

#define HMMA_M(buf, m) do {                                                    \
    _Pragma("unroll")                                                          \
    for (int n = 0; n < 8; n++) {                                              \
        const int pr = n >> 1, ro = (n & 1) * 2;                               \
        asm volatile(                                                          \
            "mma.sync.aligned.m16n8k16.row.col.f32.bf16.bf16.f32 "             \
            "{%0,%1,%2,%3}, {%4,%5,%6,%7}, {%8,%9}, {%0,%1,%2,%3};"            \
            : "+f"(acc[m][n][0]), "+f"(acc[m][n][1]),                          \
              "+f"(acc[m][n][2]), "+f"(acc[m][n][3])                           \
            : "r"(fa[buf][m][0]), "r"(fa[buf][m][1]),                          \
              "r"(fa[buf][m][2]), "r"(fa[buf][m][3]),                          \
              "r"(fb[buf][pr][ro]), "r"(fb[buf][pr][ro + 1]));                 \
    }                                                                          \
} while (0)

#define STEP(ldbuf, base, ks, mmabuf) do {                                     \
    LDSM_B1(ldbuf, base, ks, 0); LDSM_B1(ldbuf, base, ks, 1);                  \
    HMMA_M(mmabuf, 0);                                                         \
    LDSM_B1(ldbuf, base, ks, 2); LDSM_B1(ldbuf, base, ks, 3);                  \
    HMMA_M(mmabuf, 1);                                                         \
    LDSM_A1(ldbuf, base, ks, 0); LDSM_A1(ldbuf, base, ks, 1);                  \
    HMMA_M(mmabuf, 2);                                                         \
    LDSM_A1(ldbuf, base, ks, 2); LDSM_A1(ldbuf, base, ks, 3);                  \
    HMMA_M(mmabuf, 3);                                                         \
} while (0)

    LOAD_TILE(0);
    LOAD_TILE(1);
    asm volatile("cp.async.wait_group 1;");
    __syncthreads();
    {
        const uint32_t b0 = smaddr(sm);
        #pragma unroll
        for (int m = 0; m < 4; m++) LDSM_A1(0, b0, 0, m);
        #pragma unroll
        for (int pr = 0; pr < 4; pr++) LDSM_B1(0, b0, 0, pr);
    }

    #pragma unroll 1
    for (int kt = 0; kt < NKT; kt++) {
        const uint32_t abase = smaddr(sm + (kt % NSTAGE) * STAGE_B);
        STEP(1, abase, 1, 0);
        STEP(0, abase, 2, 1);
        STEP(1, abase, 3, 0);
        if (kt + 2 < NKT) LOAD_TILE(kt + 2);
        if (kt + 1 < NKT) {
            if (kt + 2 < NKT) asm volatile("cp.async.wait_group 1;");
            else              asm volatile("cp.async.wait_group 0;");
            __syncthreads();
            const uint32_t nbase = smaddr(sm + ((kt + 1) % NSTAGE) * STAGE_B);
            STEP(0, nbase, 0, 1);
        } else {
            #pragma unroll
            for (int m = 0; m < 4; m++) HMMA_M(1, m);
        }
    }
#undef LOAD_TILE
#undef LDSM_A1
#undef LDSM_B1
#undef HMMA_M
#undef STEP

    // ---- epilogue: approx dist + per-(row, 16-code subtile) min ----
    const int g  = lane >> 2;
    const int qc = lane & 3;

    float en[8][2];
    #pragma unroll
    for (int n = 0; n < 8; n++) {
        int col = n0 + warpX * 64 + n * 8 + qc * 2;
        en[n][0] = g_enorm[col];
        en[n][1] = g_enorm[col + 1];
    }

    #pragma unroll
    for (int m = 0; m < 4; m++) {
        #pragma unroll
        for (int h = 0; h < 2; h++) {
            int grow = row0 + warpY * 64 + m * 16 + g + h * 8;
            float Ar = g_rowA[grow];
            #pragma unroll
            for (int s = 0; s < 4; s++) {
                float v = 3.402823466e+38f;
                #pragma unroll
                for (int nn = 0; nn < 2; nn++) {
                    int n = s * 2 + nn;
                    #pragma unroll
                    for (int p = 0; p < 2; p++) {
                        float d = Ar - 2.0f * acc[m][n][h * 2 + p] + en[n][p];
                        v = fminf(v, d);
                    }
                }
                v = fminf(v, __shfl_xor_sync(0xFFFFFFFF, v, 1));
                v = fminf(v, __shfl_xor_sync(0xFFFFFFFF, v, 2));
                if (qc == 0)
                    g_tilemin[(size_t)grow * NTILES + blockIdx.y * 8 + warpX * 4 + s] = v;
            }
        }
    }
}

// ---------------------------------------------------------------------------
// Pass 1: candidate selection (R14, proven). Appends rows to tile lists.
// ---------------------------------------------------------------------------
__global__ void __launch_bounds__(256) candsel_kernel() {
    const int wid  = threadIdx.x >> 5;
    const int lane = threadIdx.x & 31;
    const int row  = blockIdx.x * 8 + wid;

    float tm[16];
    #pragma unroll
    for (int j = 0; j < 16; j++)
        tm[j] = g_tilemin[(size_t)row * NTILES + lane + 32 * j];

    float rmin = tm[0];
    #pragma unroll
    for (int j = 1; j < 16; j++) rmin = fminf(rmin, tm[j]);
    #pragma unroll
    for (int o = 16; o > 0; o >>= 1)
        rmin = fminf(rmin, __shfl_xor_sync(0xFFFFFFFF, rmin, o));

    if (lane == 0) g_best[row] = 0xFFFFFFFFFFFFFFFFull;

    const float thr = rmin + MARGIN;
    #pragma unroll
    for (int j = 0; j < 16; j++) {
        int tile = lane + 32 * j;
        if (tm[j] <= thr) {
            int pos = atomicAdd(&g_tcnt[tile], 1);
            g_lists[(size_t)tile * R_TOTAL + pos] = row;
        }
    }
}

// ---------------------------------------------------------------------------
// Pass 2: tile-major exact rescore (R14 structure). NEW: float4 loads for z
// (broadcast LDG.128) and codes (smem rows padded to 516 floats, 16B-aligned)
// — 4x fewer load instructions; the fmaf chain unpacks x,y,z,w in order so
// the rounding sequence is bit-identical to the scalar ascending-k chain.
// Merge via atomicMin on packed (dist_bits, code) u64 == lex (val, idx).
// ---------------------------------------------------------------------------
#define P2_CHUNKS 32
#define EPAD 516
__global__ void __launch_bounds__(256) rescore2_kernel(
    const float* __restrict__ z,
    const float* __restrict__ embed)
{
    const int tile  = blockIdx.x;
    const int count = g_tcnt[tile];
    const int first = blockIdx.y * 16;
    if (first >= count) return;

    __shared__ __align__(16) float ecod[16 * EPAD];
    for (int idx = threadIdx.x; idx < 16 * DDIM; idx += 256) {
        int r = idx >> 9, k = idx & 511;
        ecod[r * EPAD + k] = embed[((size_t)tile * 16 + r) * DDIM + k];
    }
    __syncthreads();

    const int wid  = threadIdx.x >> 5;
    const int lane = threadIdx.x & 31;
    const int half = lane >> 4;
    const int l16  = lane & 15;
    const int slot = wid * 2 + half;            // 0..15
    const int code = tile * 16 + l16;
    const float C  = g_enorm[code];
    const float4* ec4 = (const float4*)(ecod + l16 * EPAD);

    for (int i = first + slot; i < count; i += P2_CHUNKS * 16) {
        const int row = g_lists[(size_t)tile * R_TOTAL + i];
        const float4* zr4 = (const float4*)(z + (size_t)row * DDIM);
        const float A = g_rowA[row];
        float dot = 0.0f;
        #pragma unroll 8
        for (int k4 = 0; k4 < DDIM / 4; k4++) {
            float4 zv = zr4[k4];
            float4 ev = ec4[k4];
            dot = fmaf(zv.x, ev.x, dot);
            dot = fmaf(zv.y, ev.y, dot);
            dot = fmaf(zv.z, ev.z, dot);
            dot = fmaf(zv.w, ev.w, dot);
        }
        float B2   = 2.0f * dot;
        float tt   = __fadd_rn(A, -B2);
        float dist = __fadd_rn(tt, C);

        // 16-lane lexicographic argmin within the half-warp
        float bv = dist;
        int   bi = code;
        #pragma unroll
        for (int o = 8; o > 0; o >>= 1) {
            float ov = __shfl_xor_sync(0xFFFFFFFF, bv, o);
            int   oi = __shfl_xor_sync(0xFFFFFFFF, bi, o);
            if (ov < bv || (ov == bv && oi < bi)) { bv = ov; bi = oi; }
        }
        if (l16 == 0) {
            unsigned long long pk =
                ((unsigned long long)__float_as_uint(bv) << 32) | (unsigned)bi;
            atomicMin(&g_best[row], pk);
        }
    }
}

// ---------------------------------------------------------------------------
// Pass 3: finalize — unpack best code, gather z_q, loss partial, codes out.
// ---------------------------------------------------------------------------
__global__ void gather_kernel(const float* __restrict__ z,
                              const float* __restrict__ embed,
                              float* __restrict__ out_zq,
                              float* __restrict__ codes_f) {
    const int row = blockIdx.x;
    const int t   = threadIdx.x;
    const int c   = (int)(g_best[row] & 0xFFFFFFFFull);
    if (t == 0 && codes_f) codes_f[row] = (float)c;
    float4 e  = *(const float4*)(embed + (size_t)c * DDIM + t * 4);
    float4 zz = *(const float4*)(z + (size_t)row * DDIM + t * 4);
    *(float4*)(out_zq + (size_t)row * DDIM + t * 4) = e;
    float dx = zz.x - e.x, dy = zz.y - e.y, dz = zz.z - e.z, dw = zz.w - e.w;
    float s = dx * dx + dy * dy + dz * dz + dw * dw;
    __shared__ float red[128];
    red[t] = s;
    __syncthreads();
    #pragma unroll
    for (int o = 64; o > 0; o >>= 1) {
        if (t < o) red[t] += red[t + o];
        __syncthreads();
    }
    if (t == 0) g_rowpart[row] = red[0];
}

__global__ void loss_kernel(float* __restrict__ out_loss) {
    const int t = threadIdx.x;
    float s = 0.0f;
    for (int i = t; i < R_TOTAL; i += 1024) s += g_rowpart[i];
    __shared__ float red[1024];
    red[t] = s;
    __syncthreads();
    for (int o = 512; o > 0; o >>= 1) {
        if (t < o) red[t] += red[t + o];
        __syncthreads();
    }
    if (t == 0) out_loss[0] = 0.1f * (red[0] / 16777216.0f);
}

// ---------------------------------------------------------------------------
extern "C" void kernel_launch(void* const* d_in, const int* in_sizes, int n_in,
                              void* d_out, int out_size) {
    const float* z     = (const float*)d_in[0];   // (8,4096,512) f32
    const float* embed = (const float*)d_in[1];   // (8192,512) f32
    float* out = (float*)d_out;

    const long long ZQ_ELEMS = (long long)R_TOTAL * DDIM;
    float* out_zq    = out;
    float* out_codes = 0;
    float* out_loss  = 0;
    if ((long long)out_size >= ZQ_ELEMS + R_TOTAL + 1) {
        out_codes = out + ZQ_ELEMS;
        out_loss  = out + ZQ_ELEMS + R_TOTAL;
    }

    static int init_done = 0;
    if (!init_done) {
        cudaFuncSetAttribute(screen_gemm_kernel,
                             cudaFuncAttributeMaxDynamicSharedMemorySize, SM_TOTAL);
        init_done = 1;
    }

    const int NCONV = (R_TOTAL * DDIM + KCODES * DDIM) / 4;
    convert_kernel<<<(NCONV + 255) / 256, 256>>>(z, embed);

    rownorm_kernel<<<((R_TOTAL + KCODES) * 4 + 255) / 256, 256>>>(z, embed);

    dim3 gg(R_TOTAL / 128, KCODES / 128);   // (256, 64)
    screen_gemm_kernel<<<gg, 128, SM_TOTAL>>>();

    candsel_kernel<<<R_TOTAL / 8, 256>>>();

    rescore2_kernel<<<dim3(NTILES, P2_CHUNKS), 256>>>(z, embed);

    gather_kernel<<<R_TOTAL, 128>>>(z, embed, out_zq, out_codes);

    if (out_loss) loss_kernel<<<1, 1024>>>(out_loss);
}